// round 8
// baseline (speedup 1.0000x reference)
#include <cuda_runtime.h>

// Problem-fixed sizes (from reference setup_inputs).
#define MAX_N_VARS    1000000
#define MAX_N_CONSTRS 1000000
#define FULLMASK 0xffffffffu

// Scratch (allocs forbidden -> __device__ globals).
__device__ float g_values[MAX_N_VARS];
__device__ float g_ax[MAX_N_CONSTRS];

// ---- L2 eviction-priority helper (kept on prep stores; cheap) --------------
__device__ __forceinline__ unsigned long long mk_evict_last_policy() {
    unsigned long long pol;
    asm volatile("createpolicy.fractional.L2::evict_last.b64 %0, 1.0;" : "=l"(pol));
    return pol;
}
__device__ __forceinline__ void st_policy_f4(float* p, float4 v,
                                             unsigned long long pol) {
    asm volatile("st.global.L2::cache_hint.v4.f32 [%0], {%1,%2,%3,%4}, %5;"
                 :: "l"(p), "f"(v.x), "f"(v.y), "f"(v.z), "f"(v.w), "l"(pol)
                 : "memory");
}

// ---------------------------------------------------------------------------
// Kernel 1: values = pred*(ub-lb)+lb ; zero ax ; zero out scalar.
// 1 float4 per thread (R6 configuration — fastest measured).
// ---------------------------------------------------------------------------
__global__ void prep_kernel(const float4* __restrict__ pred,
                            const float4* __restrict__ lb,
                            const float4* __restrict__ ub,
                            int n_vars4, int n_constrs4,
                            float* __restrict__ out) {
    unsigned long long pol = mk_evict_last_policy();
    int i = blockIdx.x * blockDim.x + threadIdx.x;
    if (i < n_vars4) {
        float4 p = __ldcg(pred + i);
        float4 l = __ldcg(lb + i);
        float4 u = __ldcg(ub + i);
        float4 v;
        v.x = fmaf(p.x, u.x - l.x, l.x);
        v.y = fmaf(p.y, u.y - l.y, l.y);
        v.z = fmaf(p.z, u.z - l.z, l.z);
        v.w = fmaf(p.w, u.w - l.w, l.w);
        st_policy_f4(g_values + 4 * i, v, pol);
    }
    if (i < n_constrs4) {
        st_policy_f4(g_ax + 4 * i, make_float4(0.f, 0.f, 0.f, 0.f), pol);
    }
    if (i == 0) out[0] = 0.0f;
}

// ---------------------------------------------------------------------------
// Kernel 2: segmented scatter-add (R6 structure). constr_idx sorted ->
// run-length aggregate locally. Gathers via __ldcg (L2-only, no L1 alloc).
// ITEMS=16: halves stream LDG instr count + atomics vs ITEMS=8, doubles
// per-thread gather MLP; ~24 warps/SM remain (occupancy shown insensitive).
// ---------------------------------------------------------------------------
#define ITEMS 16

__global__ void __launch_bounds__(256)
spmv_kernel(const float* __restrict__ coeff,
            const int*   __restrict__ cidx,
            const int*   __restrict__ vidx,
            int nnz) {
    long long base = (long long)(blockIdx.x * blockDim.x + threadIdx.x) * ITEMS;
    if (base >= nnz) return;

    float c[ITEMS];
    int   ci[ITEMS];

    if (base + ITEMS <= nnz) {
        // ---- full tile: predicate-free ----
        int vi[ITEMS];
#pragma unroll
        for (int j = 0; j < ITEMS; j += 4) {
            float4 f = *reinterpret_cast<const float4*>(coeff + base + j);
            int4   a = *reinterpret_cast<const int4*>(cidx + base + j);
            int4   b = *reinterpret_cast<const int4*>(vidx + base + j);
            c[j + 0] = f.x; c[j + 1] = f.y; c[j + 2] = f.z; c[j + 3] = f.w;
            ci[j + 0] = a.x; ci[j + 1] = a.y; ci[j + 2] = a.z; ci[j + 3] = a.w;
            vi[j + 0] = b.x; vi[j + 1] = b.y; vi[j + 2] = b.z; vi[j + 3] = b.w;
        }
        // Gathers: L2-only, all 16 in flight before any use.
#pragma unroll
        for (int j = 0; j < ITEMS; j++) {
            c[j] = c[j] * __ldcg(g_values + vi[j]);
        }
        int   cur = ci[0];
        float acc = c[0];
#pragma unroll
        for (int j = 1; j < ITEMS; j++) {
            if (ci[j] == cur) {
                acc += c[j];
            } else {
                atomicAdd(&g_ax[cur], acc);
                cur = ci[j];
                acc = c[j];
            }
        }
        atomicAdd(&g_ax[cur], acc);
    } else {
        // ---- tail tile ----
        int count = (int)(nnz - base);
        for (int j = 0; j < count; j++) {
            c[j]  = coeff[base + j] * __ldcg(g_values + vidx[base + j]);
            ci[j] = cidx[base + j];
        }
        int   cur = ci[0];
        float acc = c[0];
        for (int j = 1; j < count; j++) {
            if (ci[j] == cur) {
                acc += c[j];
            } else {
                atomicAdd(&g_ax[cur], acc);
                cur = ci[j];
                acc = c[j];
            }
        }
        atomicAdd(&g_ax[cur], acc);
    }
}

// ---------------------------------------------------------------------------
// Kernel 3: violations + mean reduction (vectorized, __ldcg on read-once).
// sense: 1 -> relu(ax-b), 2 -> relu(b-ax), 3 -> |ax-b|, else 0.
// ---------------------------------------------------------------------------
__global__ void loss_kernel(const float4* __restrict__ rhs,
                            const int4*   __restrict__ sense,
                            int n_constrs4, float inv_n,
                            float* __restrict__ out) {
    __shared__ float sdata[32];
    float local = 0.0f;
    int stride = gridDim.x * blockDim.x;
    const float4* ax4 = reinterpret_cast<const float4*>(g_ax);
    for (int i = blockIdx.x * blockDim.x + threadIdx.x; i < n_constrs4; i += stride) {
        float4 a = __ldcg(ax4 + i);
        float4 r = __ldcg(rhs + i);
        int4   s = __ldcg(sense + i);
        float d0 = a.x - r.x, d1 = a.y - r.y, d2 = a.z - r.z, d3 = a.w - r.w;
        float v;
        v = (s.x == 1) ? fmaxf(d0, 0.f) : (s.x == 2) ? fmaxf(-d0, 0.f) : (s.x == 3) ? fabsf(d0) : 0.f;
        local += v;
        v = (s.y == 1) ? fmaxf(d1, 0.f) : (s.y == 2) ? fmaxf(-d1, 0.f) : (s.y == 3) ? fabsf(d1) : 0.f;
        local += v;
        v = (s.z == 1) ? fmaxf(d2, 0.f) : (s.z == 2) ? fmaxf(-d2, 0.f) : (s.z == 3) ? fabsf(d2) : 0.f;
        local += v;
        v = (s.w == 1) ? fmaxf(d3, 0.f) : (s.w == 2) ? fmaxf(-d3, 0.f) : (s.w == 3) ? fabsf(d3) : 0.f;
        local += v;
    }
#pragma unroll
    for (int off = 16; off > 0; off >>= 1)
        local += __shfl_down_sync(FULLMASK, local, off);
    int lane = threadIdx.x & 31;
    int wid  = threadIdx.x >> 5;
    if (lane == 0) sdata[wid] = local;
    __syncthreads();
    int nwarps = (blockDim.x + 31) >> 5;
    if (wid == 0) {
        float v = (lane < nwarps) ? sdata[lane] : 0.0f;
#pragma unroll
        for (int off = 16; off > 0; off >>= 1)
            v += __shfl_down_sync(FULLMASK, v, off);
        if (lane == 0) atomicAdd(out, v * inv_n);
    }
}

// Tail-handling loss kernel for n_constrs not divisible by 4 (safety).
__global__ void loss_tail_kernel(const float* __restrict__ rhs,
                                 const int*   __restrict__ sense,
                                 int start, int n_constrs, float inv_n,
                                 float* __restrict__ out) {
    int i = start + blockIdx.x * blockDim.x + threadIdx.x;
    if (i < n_constrs) {
        float diff = g_ax[i] - rhs[i];
        int s = sense[i];
        float v = (s == 1) ? fmaxf(diff, 0.f)
                : (s == 2) ? fmaxf(-diff, 0.f)
                : (s == 3) ? fabsf(diff) : 0.f;
        atomicAdd(out, v * inv_n);
    }
}

// ---------------------------------------------------------------------------
// Launch. Input order: pred, coeff, constr_rhs, var_lb, var_ub,
// constr_idx, var_idx, constr_sense, n_vars, n_constrs.
// ---------------------------------------------------------------------------
extern "C" void kernel_launch(void* const* d_in, const int* in_sizes, int n_in,
                              void* d_out, int out_size) {
    const float* pred  = (const float*)d_in[0];
    const float* coeff = (const float*)d_in[1];
    const float* rhs   = (const float*)d_in[2];
    const float* lb    = (const float*)d_in[3];
    const float* ub    = (const float*)d_in[4];
    const int*   cidx  = (const int*)d_in[5];
    const int*   vidx  = (const int*)d_in[6];
    const int*   sense = (const int*)d_in[7];

    int n_vars    = in_sizes[0];
    int nnz       = in_sizes[1];
    int n_constrs = in_sizes[2];

    float* out = (float*)d_out;
    int threads = 256;

    // prep: vectorized (problem sizes are multiples of 4).
    int n_vars4    = n_vars / 4;
    int n_constrs4 = n_constrs / 4;
    int n_max4 = n_vars4 > n_constrs4 ? n_vars4 : n_constrs4;
    prep_kernel<<<(n_max4 + threads - 1) / threads, threads>>>(
        (const float4*)pred, (const float4*)lb, (const float4*)ub,
        n_vars4, n_constrs4, out);

    long long n_threads_spmv = ((long long)nnz + ITEMS - 1) / ITEMS;
    int blocks_spmv = (int)((n_threads_spmv + threads - 1) / threads);
    spmv_kernel<<<blocks_spmv, threads>>>(coeff, cidx, vidx, nnz);

    float inv_n = 1.0f / (float)n_constrs;
    int blocks_loss = 1184;  // 8 * 148 SMs
    loss_kernel<<<blocks_loss, threads>>>((const float4*)rhs, (const int4*)sense,
                                          n_constrs4, inv_n, out);
    int tail_start = n_constrs4 * 4;
    if (tail_start < n_constrs) {
        int tail = n_constrs - tail_start;
        loss_tail_kernel<<<(tail + threads - 1) / threads, threads>>>(
            rhs, sense, tail_start, n_constrs, inv_n, out);
    }
}

// round 9
// speedup vs baseline: 1.1276x; 1.1276x over previous
#include <cuda_runtime.h>

// Problem-fixed sizes (from reference setup_inputs).
#define MAX_N_VARS    1000000
#define MAX_N_CONSTRS 1000000
#define FULLMASK 0xffffffffu

// Scratch (allocs forbidden -> __device__ globals).
__device__ float g_values[MAX_N_VARS];
__device__ float g_ax[MAX_N_CONSTRS];

// ---- L2 eviction-priority helper (kept on prep stores; cheap) --------------
__device__ __forceinline__ unsigned long long mk_evict_last_policy() {
    unsigned long long pol;
    asm volatile("createpolicy.fractional.L2::evict_last.b64 %0, 1.0;" : "=l"(pol));
    return pol;
}
__device__ __forceinline__ void st_policy_f4(float* p, float4 v,
                                             unsigned long long pol) {
    asm volatile("st.global.L2::cache_hint.v4.f32 [%0], {%1,%2,%3,%4}, %5;"
                 :: "l"(p), "f"(v.x), "f"(v.y), "f"(v.z), "f"(v.w), "l"(pol)
                 : "memory");
}

// ---------------------------------------------------------------------------
// Kernel 1: values = pred*(ub-lb)+lb ; zero ax ; zero out scalar.
// ---------------------------------------------------------------------------
__global__ void prep_kernel(const float4* __restrict__ pred,
                            const float4* __restrict__ lb,
                            const float4* __restrict__ ub,
                            int n_vars4, int n_constrs4,
                            float* __restrict__ out) {
    unsigned long long pol = mk_evict_last_policy();
    int i = blockIdx.x * blockDim.x + threadIdx.x;
    if (i < n_vars4) {
        float4 p = __ldcg(pred + i);
        float4 l = __ldcg(lb + i);
        float4 u = __ldcg(ub + i);
        float4 v;
        v.x = fmaf(p.x, u.x - l.x, l.x);
        v.y = fmaf(p.y, u.y - l.y, l.y);
        v.z = fmaf(p.z, u.z - l.z, l.z);
        v.w = fmaf(p.w, u.w - l.w, l.w);
        st_policy_f4(g_values + 4 * i, v, pol);
    }
    if (i < n_constrs4) {
        st_policy_f4(g_ax + 4 * i, make_float4(0.f, 0.f, 0.f, 0.f), pol);
    }
    if (i == 0) out[0] = 0.0f;
}

// ---------------------------------------------------------------------------
// Kernel 2: segmented scatter-add — R6 champion structure (ITEMS=8).
// constr_idx sorted -> run-length aggregate locally. ALL loads bypass L1:
// gathers via __ldcg (won -19us in R6: no L1 fill at ~5% hit rate), streams
// via __ldcg (read-once, zero L1 reuse -> fill is pure overhead).
// ---------------------------------------------------------------------------
#define ITEMS 8

__global__ void __launch_bounds__(256)
spmv_kernel(const float* __restrict__ coeff,
            const int*   __restrict__ cidx,
            const int*   __restrict__ vidx,
            int nnz) {
    long long base = (long long)(blockIdx.x * blockDim.x + threadIdx.x) * ITEMS;
    if (base >= nnz) return;

    float c[ITEMS];
    int   ci[ITEMS];

    if (base + ITEMS <= nnz) {
        // ---- full tile: predicate-free ----
        int vi[ITEMS];
#pragma unroll
        for (int j = 0; j < ITEMS; j += 4) {
            float4 f = __ldcg(reinterpret_cast<const float4*>(coeff + base + j));
            int4   a = __ldcg(reinterpret_cast<const int4*>(cidx + base + j));
            int4   b = __ldcg(reinterpret_cast<const int4*>(vidx + base + j));
            c[j + 0] = f.x; c[j + 1] = f.y; c[j + 2] = f.z; c[j + 3] = f.w;
            ci[j + 0] = a.x; ci[j + 1] = a.y; ci[j + 2] = a.z; ci[j + 3] = a.w;
            vi[j + 0] = b.x; vi[j + 1] = b.y; vi[j + 2] = b.z; vi[j + 3] = b.w;
        }
        // Gathers: L2-only, all 8 in flight before any use.
#pragma unroll
        for (int j = 0; j < ITEMS; j++) {
            c[j] = c[j] * __ldcg(g_values + vi[j]);
        }
        int   cur = ci[0];
        float acc = c[0];
#pragma unroll
        for (int j = 1; j < ITEMS; j++) {
            if (ci[j] == cur) {
                acc += c[j];
            } else {
                atomicAdd(&g_ax[cur], acc);
                cur = ci[j];
                acc = c[j];
            }
        }
        atomicAdd(&g_ax[cur], acc);
    } else {
        // ---- tail tile ----
        int count = (int)(nnz - base);
        for (int j = 0; j < count; j++) {
            c[j]  = coeff[base + j] * __ldcg(g_values + vidx[base + j]);
            ci[j] = cidx[base + j];
        }
        int   cur = ci[0];
        float acc = c[0];
        for (int j = 1; j < count; j++) {
            if (ci[j] == cur) {
                acc += c[j];
            } else {
                atomicAdd(&g_ax[cur], acc);
                cur = ci[j];
                acc = c[j];
            }
        }
        atomicAdd(&g_ax[cur], acc);
    }
}

// ---------------------------------------------------------------------------
// Kernel 3: violations + mean reduction (vectorized, __ldcg on read-once).
// sense: 1 -> relu(ax-b), 2 -> relu(b-ax), 3 -> |ax-b|, else 0.
// ---------------------------------------------------------------------------
__global__ void loss_kernel(const float4* __restrict__ rhs,
                            const int4*   __restrict__ sense,
                            int n_constrs4, float inv_n,
                            float* __restrict__ out) {
    __shared__ float sdata[32];
    float local = 0.0f;
    int stride = gridDim.x * blockDim.x;
    const float4* ax4 = reinterpret_cast<const float4*>(g_ax);
    for (int i = blockIdx.x * blockDim.x + threadIdx.x; i < n_constrs4; i += stride) {
        float4 a = __ldcg(ax4 + i);
        float4 r = __ldcg(rhs + i);
        int4   s = __ldcg(sense + i);
        float d0 = a.x - r.x, d1 = a.y - r.y, d2 = a.z - r.z, d3 = a.w - r.w;
        float v;
        v = (s.x == 1) ? fmaxf(d0, 0.f) : (s.x == 2) ? fmaxf(-d0, 0.f) : (s.x == 3) ? fabsf(d0) : 0.f;
        local += v;
        v = (s.y == 1) ? fmaxf(d1, 0.f) : (s.y == 2) ? fmaxf(-d1, 0.f) : (s.y == 3) ? fabsf(d1) : 0.f;
        local += v;
        v = (s.z == 1) ? fmaxf(d2, 0.f) : (s.z == 2) ? fmaxf(-d2, 0.f) : (s.z == 3) ? fabsf(d2) : 0.f;
        local += v;
        v = (s.w == 1) ? fmaxf(d3, 0.f) : (s.w == 2) ? fmaxf(-d3, 0.f) : (s.w == 3) ? fabsf(d3) : 0.f;
        local += v;
    }
#pragma unroll
    for (int off = 16; off > 0; off >>= 1)
        local += __shfl_down_sync(FULLMASK, local, off);
    int lane = threadIdx.x & 31;
    int wid  = threadIdx.x >> 5;
    if (lane == 0) sdata[wid] = local;
    __syncthreads();
    int nwarps = (blockDim.x + 31) >> 5;
    if (wid == 0) {
        float v = (lane < nwarps) ? sdata[lane] : 0.0f;
#pragma unroll
        for (int off = 16; off > 0; off >>= 1)
            v += __shfl_down_sync(FULLMASK, v, off);
        if (lane == 0) atomicAdd(out, v * inv_n);
    }
}

// Tail-handling loss kernel for n_constrs not divisible by 4 (safety).
__global__ void loss_tail_kernel(const float* __restrict__ rhs,
                                 const int*   __restrict__ sense,
                                 int start, int n_constrs, float inv_n,
                                 float* __restrict__ out) {
    int i = start + blockIdx.x * blockDim.x + threadIdx.x;
    if (i < n_constrs) {
        float diff = g_ax[i] - rhs[i];
        int s = sense[i];
        float v = (s == 1) ? fmaxf(diff, 0.f)
                : (s == 2) ? fmaxf(-diff, 0.f)
                : (s == 3) ? fabsf(diff) : 0.f;
        atomicAdd(out, v * inv_n);
    }
}

// ---------------------------------------------------------------------------
// Launch. Input order: pred, coeff, constr_rhs, var_lb, var_ub,
// constr_idx, var_idx, constr_sense, n_vars, n_constrs.
// ---------------------------------------------------------------------------
extern "C" void kernel_launch(void* const* d_in, const int* in_sizes, int n_in,
                              void* d_out, int out_size) {
    const float* pred  = (const float*)d_in[0];
    const float* coeff = (const float*)d_in[1];
    const float* rhs   = (const float*)d_in[2];
    const float* lb    = (const float*)d_in[3];
    const float* ub    = (const float*)d_in[4];
    const int*   cidx  = (const int*)d_in[5];
    const int*   vidx  = (const int*)d_in[6];
    const int*   sense = (const int*)d_in[7];

    int n_vars    = in_sizes[0];
    int nnz       = in_sizes[1];
    int n_constrs = in_sizes[2];

    float* out = (float*)d_out;
    int threads = 256;

    // prep: vectorized (problem sizes are multiples of 4).
    int n_vars4    = n_vars / 4;
    int n_constrs4 = n_constrs / 4;
    int n_max4 = n_vars4 > n_constrs4 ? n_vars4 : n_constrs4;
    prep_kernel<<<(n_max4 + threads - 1) / threads, threads>>>(
        (const float4*)pred, (const float4*)lb, (const float4*)ub,
        n_vars4, n_constrs4, out);

    long long n_threads_spmv = ((long long)nnz + ITEMS - 1) / ITEMS;
    int blocks_spmv = (int)((n_threads_spmv + threads - 1) / threads);
    spmv_kernel<<<blocks_spmv, threads>>>(coeff, cidx, vidx, nnz);

    float inv_n = 1.0f / (float)n_constrs;
    int blocks_loss = 1184;  // 8 * 148 SMs
    loss_kernel<<<blocks_loss, threads>>>((const float4*)rhs, (const int4*)sense,
                                          n_constrs4, inv_n, out);
    int tail_start = n_constrs4 * 4;
    if (tail_start < n_constrs) {
        int tail = n_constrs - tail_start;
        loss_tail_kernel<<<(tail + threads - 1) / threads, threads>>>(
            rhs, sense, tail_start, n_constrs, inv_n, out);
    }
}

// round 10
// speedup vs baseline: 1.1572x; 1.0263x over previous
#include <cuda_runtime.h>

// Problem-fixed sizes (from reference setup_inputs).
#define MAX_N_VARS    1000000
#define MAX_N_CONSTRS 1000000
#define FULLMASK 0xffffffffu

// Scratch (allocs forbidden -> __device__ globals).
__device__ float g_values[MAX_N_VARS];
__device__ float g_ax[MAX_N_CONSTRS];

// ---- L2 eviction-priority helper (kept on prep stores; cheap) --------------
__device__ __forceinline__ unsigned long long mk_evict_last_policy() {
    unsigned long long pol;
    asm volatile("createpolicy.fractional.L2::evict_last.b64 %0, 1.0;" : "=l"(pol));
    return pol;
}
__device__ __forceinline__ void st_policy_f4(float* p, float4 v,
                                             unsigned long long pol) {
    asm volatile("st.global.L2::cache_hint.v4.f32 [%0], {%1,%2,%3,%4}, %5;"
                 :: "l"(p), "f"(v.x), "f"(v.y), "f"(v.z), "f"(v.w), "l"(pol)
                 : "memory");
}

// ---------------------------------------------------------------------------
// Kernel 1: values = pred*(ub-lb)+lb ; zero ax ; zero out scalar.
// ---------------------------------------------------------------------------
__global__ void prep_kernel(const float4* __restrict__ pred,
                            const float4* __restrict__ lb,
                            const float4* __restrict__ ub,
                            int n_vars4, int n_constrs4,
                            float* __restrict__ out) {
    unsigned long long pol = mk_evict_last_policy();
    int i = blockIdx.x * blockDim.x + threadIdx.x;
    if (i < n_vars4) {
        float4 p = __ldcg(pred + i);
        float4 l = __ldcg(lb + i);
        float4 u = __ldcg(ub + i);
        float4 v;
        v.x = fmaf(p.x, u.x - l.x, l.x);
        v.y = fmaf(p.y, u.y - l.y, l.y);
        v.z = fmaf(p.z, u.z - l.z, l.z);
        v.w = fmaf(p.w, u.w - l.w, l.w);
        st_policy_f4(g_values + 4 * i, v, pol);
    }
    if (i < n_constrs4) {
        st_policy_f4(g_ax + 4 * i, make_float4(0.f, 0.f, 0.f, 0.f), pol);
    }
    if (i == 0) out[0] = 0.0f;
}

// ---------------------------------------------------------------------------
// Kernel 2: segmented scatter-add — R6 champion configuration.
// constr_idx sorted -> run-length aggregate locally (~1.5 atomics / 8 nnz).
// Streams: PLAIN vector loads (L1 path; __ldcg regressed in R9).
// Gathers: __ldcg (L2-only, no L1 alloc at ~5% hit rate; won -19us in R6).
// 32-bit indexing throughout (nnz = 16M fits int; shorter address chains).
// ---------------------------------------------------------------------------
#define ITEMS 8

__global__ void __launch_bounds__(256)
spmv_kernel(const float* __restrict__ coeff,
            const int*   __restrict__ cidx,
            const int*   __restrict__ vidx,
            int nnz) {
    int base = (blockIdx.x * blockDim.x + threadIdx.x) * ITEMS;
    if (base >= nnz) return;

    float c[ITEMS];
    int   ci[ITEMS];

    if (base + ITEMS <= nnz) {
        // ---- full tile: predicate-free ----
        int vi[ITEMS];
#pragma unroll
        for (int j = 0; j < ITEMS; j += 4) {
            float4 f = *reinterpret_cast<const float4*>(coeff + base + j);
            int4   a = *reinterpret_cast<const int4*>(cidx + base + j);
            int4   b = *reinterpret_cast<const int4*>(vidx + base + j);
            c[j + 0] = f.x; c[j + 1] = f.y; c[j + 2] = f.z; c[j + 3] = f.w;
            ci[j + 0] = a.x; ci[j + 1] = a.y; ci[j + 2] = a.z; ci[j + 3] = a.w;
            vi[j + 0] = b.x; vi[j + 1] = b.y; vi[j + 2] = b.z; vi[j + 3] = b.w;
        }
        // Gathers: L2-only, all 8 in flight before any use.
#pragma unroll
        for (int j = 0; j < ITEMS; j++) {
            c[j] = c[j] * __ldcg(g_values + vi[j]);
        }
        int   cur = ci[0];
        float acc = c[0];
#pragma unroll
        for (int j = 1; j < ITEMS; j++) {
            if (ci[j] == cur) {
                acc += c[j];
            } else {
                atomicAdd(&g_ax[cur], acc);
                cur = ci[j];
                acc = c[j];
            }
        }
        atomicAdd(&g_ax[cur], acc);
    } else {
        // ---- tail tile ----
        int count = nnz - base;
        for (int j = 0; j < count; j++) {
            c[j]  = coeff[base + j] * __ldcg(g_values + vidx[base + j]);
            ci[j] = cidx[base + j];
        }
        int   cur = ci[0];
        float acc = c[0];
        for (int j = 1; j < count; j++) {
            if (ci[j] == cur) {
                acc += c[j];
            } else {
                atomicAdd(&g_ax[cur], acc);
                cur = ci[j];
                acc = c[j];
            }
        }
        atomicAdd(&g_ax[cur], acc);
    }
}

// ---------------------------------------------------------------------------
// Kernel 3: violations + mean reduction (vectorized, __ldcg on read-once).
// sense: 1 -> relu(ax-b), 2 -> relu(b-ax), 3 -> |ax-b|, else 0.
// ---------------------------------------------------------------------------
__global__ void loss_kernel(const float4* __restrict__ rhs,
                            const int4*   __restrict__ sense,
                            int n_constrs4, float inv_n,
                            float* __restrict__ out) {
    __shared__ float sdata[32];
    float local = 0.0f;
    int stride = gridDim.x * blockDim.x;
    const float4* ax4 = reinterpret_cast<const float4*>(g_ax);
    for (int i = blockIdx.x * blockDim.x + threadIdx.x; i < n_constrs4; i += stride) {
        float4 a = __ldcg(ax4 + i);
        float4 r = __ldcg(rhs + i);
        int4   s = __ldcg(sense + i);
        float d0 = a.x - r.x, d1 = a.y - r.y, d2 = a.z - r.z, d3 = a.w - r.w;
        float v;
        v = (s.x == 1) ? fmaxf(d0, 0.f) : (s.x == 2) ? fmaxf(-d0, 0.f) : (s.x == 3) ? fabsf(d0) : 0.f;
        local += v;
        v = (s.y == 1) ? fmaxf(d1, 0.f) : (s.y == 2) ? fmaxf(-d1, 0.f) : (s.y == 3) ? fabsf(d1) : 0.f;
        local += v;
        v = (s.z == 1) ? fmaxf(d2, 0.f) : (s.z == 2) ? fmaxf(-d2, 0.f) : (s.z == 3) ? fabsf(d2) : 0.f;
        local += v;
        v = (s.w == 1) ? fmaxf(d3, 0.f) : (s.w == 2) ? fmaxf(-d3, 0.f) : (s.w == 3) ? fabsf(d3) : 0.f;
        local += v;
    }
#pragma unroll
    for (int off = 16; off > 0; off >>= 1)
        local += __shfl_down_sync(FULLMASK, local, off);
    int lane = threadIdx.x & 31;
    int wid  = threadIdx.x >> 5;
    if (lane == 0) sdata[wid] = local;
    __syncthreads();
    int nwarps = (blockDim.x + 31) >> 5;
    if (wid == 0) {
        float v = (lane < nwarps) ? sdata[lane] : 0.0f;
#pragma unroll
        for (int off = 16; off > 0; off >>= 1)
            v += __shfl_down_sync(FULLMASK, v, off);
        if (lane == 0) atomicAdd(out, v * inv_n);
    }
}

// Tail-handling loss kernel for n_constrs not divisible by 4 (safety).
__global__ void loss_tail_kernel(const float* __restrict__ rhs,
                                 const int*   __restrict__ sense,
                                 int start, int n_constrs, float inv_n,
                                 float* __restrict__ out) {
    int i = start + blockIdx.x * blockDim.x + threadIdx.x;
    if (i < n_constrs) {
        float diff = g_ax[i] - rhs[i];
        int s = sense[i];
        float v = (s == 1) ? fmaxf(diff, 0.f)
                : (s == 2) ? fmaxf(-diff, 0.f)
                : (s == 3) ? fabsf(diff) : 0.f;
        atomicAdd(out, v * inv_n);
    }
}

// ---------------------------------------------------------------------------
// Launch. Input order: pred, coeff, constr_rhs, var_lb, var_ub,
// constr_idx, var_idx, constr_sense, n_vars, n_constrs.
// ---------------------------------------------------------------------------
extern "C" void kernel_launch(void* const* d_in, const int* in_sizes, int n_in,
                              void* d_out, int out_size) {
    const float* pred  = (const float*)d_in[0];
    const float* coeff = (const float*)d_in[1];
    const float* rhs   = (const float*)d_in[2];
    const float* lb    = (const float*)d_in[3];
    const float* ub    = (const float*)d_in[4];
    const int*   cidx  = (const int*)d_in[5];
    const int*   vidx  = (const int*)d_in[6];
    const int*   sense = (const int*)d_in[7];

    int n_vars    = in_sizes[0];
    int nnz       = in_sizes[1];
    int n_constrs = in_sizes[2];

    float* out = (float*)d_out;
    int threads = 256;

    // prep: vectorized (problem sizes are multiples of 4).
    int n_vars4    = n_vars / 4;
    int n_constrs4 = n_constrs / 4;
    int n_max4 = n_vars4 > n_constrs4 ? n_vars4 : n_constrs4;
    prep_kernel<<<(n_max4 + threads - 1) / threads, threads>>>(
        (const float4*)pred, (const float4*)lb, (const float4*)ub,
        n_vars4, n_constrs4, out);

    long long n_threads_spmv = ((long long)nnz + ITEMS - 1) / ITEMS;
    int blocks_spmv = (int)((n_threads_spmv + threads - 1) / threads);
    spmv_kernel<<<blocks_spmv, threads>>>(coeff, cidx, vidx, nnz);

    float inv_n = 1.0f / (float)n_constrs;
    int blocks_loss = 1184;  // 8 * 148 SMs
    loss_kernel<<<blocks_loss, threads>>>((const float4*)rhs, (const int4*)sense,
                                          n_constrs4, inv_n, out);
    int tail_start = n_constrs4 * 4;
    if (tail_start < n_constrs) {
        int tail = n_constrs - tail_start;
        loss_tail_kernel<<<(tail + threads - 1) / threads, threads>>>(
            rhs, sense, tail_start, n_constrs, inv_n, out);
    }
}

// round 11
// speedup vs baseline: 1.1767x; 1.0169x over previous
#include <cuda_runtime.h>

// Problem-fixed sizes (from reference setup_inputs).
#define MAX_N_VARS    1000000
#define MAX_N_CONSTRS 1000000
#define FULLMASK 0xffffffffu

// Scratch (allocs forbidden -> __device__ globals).
__device__ float g_values[MAX_N_VARS];
__device__ float g_ax[MAX_N_CONSTRS];

// ---- L2 eviction-priority helper (kept on prep stores; cheap) --------------
__device__ __forceinline__ unsigned long long mk_evict_last_policy() {
    unsigned long long pol;
    asm volatile("createpolicy.fractional.L2::evict_last.b64 %0, 1.0;" : "=l"(pol));
    return pol;
}
__device__ __forceinline__ void st_policy_f4(float* p, float4 v,
                                             unsigned long long pol) {
    asm volatile("st.global.L2::cache_hint.v4.f32 [%0], {%1,%2,%3,%4}, %5;"
                 :: "l"(p), "f"(v.x), "f"(v.y), "f"(v.z), "f"(v.w), "l"(pol)
                 : "memory");
}

// ---------------------------------------------------------------------------
// Kernel 1: values = pred*(ub-lb)+lb ; zero ax ; zero out scalar.
// ---------------------------------------------------------------------------
__global__ void prep_kernel(const float4* __restrict__ pred,
                            const float4* __restrict__ lb,
                            const float4* __restrict__ ub,
                            int n_vars4, int n_constrs4,
                            float* __restrict__ out) {
    unsigned long long pol = mk_evict_last_policy();
    int i = blockIdx.x * blockDim.x + threadIdx.x;
    if (i < n_vars4) {
        float4 p = __ldcg(pred + i);
        float4 l = __ldcg(lb + i);
        float4 u = __ldcg(ub + i);
        float4 v;
        v.x = fmaf(p.x, u.x - l.x, l.x);
        v.y = fmaf(p.y, u.y - l.y, l.y);
        v.z = fmaf(p.z, u.z - l.z, l.z);
        v.w = fmaf(p.w, u.w - l.w, l.w);
        st_policy_f4(g_values + 4 * i, v, pol);
    }
    if (i < n_constrs4) {
        st_policy_f4(g_ax + 4 * i, make_float4(0.f, 0.f, 0.f, 0.f), pol);
    }
    if (i == 0) out[0] = 0.0f;
}

// ---------------------------------------------------------------------------
// Kernel 2: segmented scatter-add — champion structure (ITEMS=8, plain stream
// loads, __ldcg gathers) + MINIMAL pairwise tail-merge: if my tail run
// continues into my successor's head run and the successor closes it
// (has_b), the successor absorbs my tail partial -> I skip my tail atomic.
// 4 shuffles/thread; cuts atomics ~3M -> ~2.2M (atomic lanes are L1tex
// wavefronts on the critical path).
// ---------------------------------------------------------------------------
#define ITEMS 8

__global__ void __launch_bounds__(256)
spmv_kernel(const float* __restrict__ coeff,
            const int*   __restrict__ cidx,
            const int*   __restrict__ vidx,
            int nnz) {
    int base = (blockIdx.x * blockDim.x + threadIdx.x) * ITEMS;
    unsigned lane = threadIdx.x & 31u;
    bool active = base < nnz;

    int   head_key = -1;   // sentinel: never matches a real key
    int   tail_key = -2;   // distinct sentinel
    float head_acc = 0.f;
    float tail_acc = 0.f;
    bool  has_b    = false;  // head run closed inside this tile

    if (active) {
        float c[ITEMS];
        int   ci[ITEMS];
        int count;
        if (base + ITEMS <= nnz) {
            count = ITEMS;
            int vi[ITEMS];
#pragma unroll
            for (int j = 0; j < ITEMS; j += 4) {
                float4 f = *reinterpret_cast<const float4*>(coeff + base + j);
                int4   a = *reinterpret_cast<const int4*>(cidx + base + j);
                int4   b = *reinterpret_cast<const int4*>(vidx + base + j);
                c[j + 0] = f.x; c[j + 1] = f.y; c[j + 2] = f.z; c[j + 3] = f.w;
                ci[j + 0] = a.x; ci[j + 1] = a.y; ci[j + 2] = a.z; ci[j + 3] = a.w;
                vi[j + 0] = b.x; vi[j + 1] = b.y; vi[j + 2] = b.z; vi[j + 3] = b.w;
            }
#pragma unroll
            for (int j = 0; j < ITEMS; j++)
                c[j] = c[j] * __ldcg(g_values + vi[j]);
        } else {
            count = nnz - base;
            for (int j = 0; j < count; j++) {
                c[j]  = coeff[base + j] * __ldcg(g_values + vidx[base + j]);
                ci[j] = cidx[base + j];
            }
        }

        head_key = ci[0];
        int   cur = ci[0];
        float acc = c[0];
#pragma unroll
        for (int j = 1; j < ITEMS; j++) {
            if (j < count) {
                if (ci[j] == cur) {
                    acc += c[j];
                } else {
                    if (!has_b) { head_acc = acc; has_b = true; }
                    else        atomicAdd(&g_ax[cur], acc);  // interior run
                    cur = ci[j];
                    acc = c[j];
                }
            }
        }
        tail_key = cur;
        tail_acc = acc;
    }

    // ---- pairwise cross-thread merge (all lanes participate) ----
    int   prev_tail_key = __shfl_up_sync(FULLMASK, tail_key, 1);
    float prev_tail_acc = __shfl_up_sync(FULLMASK, tail_acc, 1);
    int   next_head_key = __shfl_down_sync(FULLMASK, head_key, 1);
    int   next_has_b    = __shfl_down_sync(FULLMASK, (int)has_b, 1);

    // I absorb predecessor's tail iff it chains into my head run AND my head
    // run closes inside my tile. (Sentinels make inactive lanes never match.)
    bool take_prev = (lane > 0) && has_b && (prev_tail_key == head_key);
    // My tail is absorbed iff successor's head matches AND successor has_b.
    bool absorbed  = (lane < 31) && next_has_b && (next_head_key == tail_key);

    if (take_prev) head_acc += prev_tail_acc;

    if (active && has_b)
        atomicAdd(&g_ax[head_key], head_acc);
    if (active && !absorbed)
        atomicAdd(&g_ax[tail_key], tail_acc);
}

// ---------------------------------------------------------------------------
// Kernel 3: violations + mean reduction (vectorized, __ldcg on read-once).
// sense: 1 -> relu(ax-b), 2 -> relu(b-ax), 3 -> |ax-b|, else 0.
// ---------------------------------------------------------------------------
__global__ void loss_kernel(const float4* __restrict__ rhs,
                            const int4*   __restrict__ sense,
                            int n_constrs4, float inv_n,
                            float* __restrict__ out) {
    __shared__ float sdata[32];
    float local = 0.0f;
    int stride = gridDim.x * blockDim.x;
    const float4* ax4 = reinterpret_cast<const float4*>(g_ax);
    for (int i = blockIdx.x * blockDim.x + threadIdx.x; i < n_constrs4; i += stride) {
        float4 a = __ldcg(ax4 + i);
        float4 r = __ldcg(rhs + i);
        int4   s = __ldcg(sense + i);
        float d0 = a.x - r.x, d1 = a.y - r.y, d2 = a.z - r.z, d3 = a.w - r.w;
        float v;
        v = (s.x == 1) ? fmaxf(d0, 0.f) : (s.x == 2) ? fmaxf(-d0, 0.f) : (s.x == 3) ? fabsf(d0) : 0.f;
        local += v;
        v = (s.y == 1) ? fmaxf(d1, 0.f) : (s.y == 2) ? fmaxf(-d1, 0.f) : (s.y == 3) ? fabsf(d1) : 0.f;
        local += v;
        v = (s.z == 1) ? fmaxf(d2, 0.f) : (s.z == 2) ? fmaxf(-d2, 0.f) : (s.z == 3) ? fabsf(d2) : 0.f;
        local += v;
        v = (s.w == 1) ? fmaxf(d3, 0.f) : (s.w == 2) ? fmaxf(-d3, 0.f) : (s.w == 3) ? fabsf(d3) : 0.f;
        local += v;
    }
#pragma unroll
    for (int off = 16; off > 0; off >>= 1)
        local += __shfl_down_sync(FULLMASK, local, off);
    int lane = threadIdx.x & 31;
    int wid  = threadIdx.x >> 5;
    if (lane == 0) sdata[wid] = local;
    __syncthreads();
    int nwarps = (blockDim.x + 31) >> 5;
    if (wid == 0) {
        float v = (lane < nwarps) ? sdata[lane] : 0.0f;
#pragma unroll
        for (int off = 16; off > 0; off >>= 1)
            v += __shfl_down_sync(FULLMASK, v, off);
        if (lane == 0) atomicAdd(out, v * inv_n);
    }
}

// Tail-handling loss kernel for n_constrs not divisible by 4 (safety).
__global__ void loss_tail_kernel(const float* __restrict__ rhs,
                                 const int*   __restrict__ sense,
                                 int start, int n_constrs, float inv_n,
                                 float* __restrict__ out) {
    int i = start + blockIdx.x * blockDim.x + threadIdx.x;
    if (i < n_constrs) {
        float diff = g_ax[i] - rhs[i];
        int s = sense[i];
        float v = (s == 1) ? fmaxf(diff, 0.f)
                : (s == 2) ? fmaxf(-diff, 0.f)
                : (s == 3) ? fabsf(diff) : 0.f;
        atomicAdd(out, v * inv_n);
    }
}

// ---------------------------------------------------------------------------
// Launch. Input order: pred, coeff, constr_rhs, var_lb, var_ub,
// constr_idx, var_idx, constr_sense, n_vars, n_constrs.
// ---------------------------------------------------------------------------
extern "C" void kernel_launch(void* const* d_in, const int* in_sizes, int n_in,
                              void* d_out, int out_size) {
    const float* pred  = (const float*)d_in[0];
    const float* coeff = (const float*)d_in[1];
    const float* rhs   = (const float*)d_in[2];
    const float* lb    = (const float*)d_in[3];
    const float* ub    = (const float*)d_in[4];
    const int*   cidx  = (const int*)d_in[5];
    const int*   vidx  = (const int*)d_in[6];
    const int*   sense = (const int*)d_in[7];

    int n_vars    = in_sizes[0];
    int nnz       = in_sizes[1];
    int n_constrs = in_sizes[2];

    float* out = (float*)d_out;
    int threads = 256;

    // prep: vectorized (problem sizes are multiples of 4).
    int n_vars4    = n_vars / 4;
    int n_constrs4 = n_constrs / 4;
    int n_max4 = n_vars4 > n_constrs4 ? n_vars4 : n_constrs4;
    prep_kernel<<<(n_max4 + threads - 1) / threads, threads>>>(
        (const float4*)pred, (const float4*)lb, (const float4*)ub,
        n_vars4, n_constrs4, out);

    long long n_threads_spmv = ((long long)nnz + ITEMS - 1) / ITEMS;
    int blocks_spmv = (int)((n_threads_spmv + threads - 1) / threads);
    spmv_kernel<<<blocks_spmv, threads>>>(coeff, cidx, vidx, nnz);

    float inv_n = 1.0f / (float)n_constrs;
    int blocks_loss = 1184;  // 8 * 148 SMs
    loss_kernel<<<blocks_loss, threads>>>((const float4*)rhs, (const int4*)sense,
                                          n_constrs4, inv_n, out);
    int tail_start = n_constrs4 * 4;
    if (tail_start < n_constrs) {
        int tail = n_constrs - tail_start;
        loss_tail_kernel<<<(tail + threads - 1) / threads, threads>>>(
            rhs, sense, tail_start, n_constrs, inv_n, out);
    }
}

// round 12
// speedup vs baseline: 1.4265x; 1.2122x over previous
#include <cuda_runtime.h>

// Problem-fixed sizes (from reference setup_inputs).
#define MAX_N_VARS    1000000
#define MAX_N_CONSTRS 1000000
#define FULLMASK 0xffffffffu

// Scratch (allocs forbidden -> __device__ globals).
__device__ float g_values[MAX_N_VARS];
__device__ float g_ax[MAX_N_CONSTRS];

// ---- L2 eviction-priority helper (kept on prep stores; cheap) --------------
__device__ __forceinline__ unsigned long long mk_evict_last_policy() {
    unsigned long long pol;
    asm volatile("createpolicy.fractional.L2::evict_last.b64 %0, 1.0;" : "=l"(pol));
    return pol;
}
__device__ __forceinline__ void st_policy_f4(float* p, float4 v,
                                             unsigned long long pol) {
    asm volatile("st.global.L2::cache_hint.v4.f32 [%0], {%1,%2,%3,%4}, %5;"
                 :: "l"(p), "f"(v.x), "f"(v.y), "f"(v.z), "f"(v.w), "l"(pol)
                 : "memory");
}

// ---------------------------------------------------------------------------
// Kernel 1: values = pred*(ub-lb)+lb ; zero ax ; zero out scalar.
// ---------------------------------------------------------------------------
__global__ void prep_kernel(const float4* __restrict__ pred,
                            const float4* __restrict__ lb,
                            const float4* __restrict__ ub,
                            int n_vars4, int n_constrs4,
                            float* __restrict__ out) {
    unsigned long long pol = mk_evict_last_policy();
    int i = blockIdx.x * blockDim.x + threadIdx.x;
    if (i < n_vars4) {
        float4 p = __ldcg(pred + i);
        float4 l = __ldcg(lb + i);
        float4 u = __ldcg(ub + i);
        float4 v;
        v.x = fmaf(p.x, u.x - l.x, l.x);
        v.y = fmaf(p.y, u.y - l.y, l.y);
        v.z = fmaf(p.z, u.z - l.z, l.z);
        v.w = fmaf(p.w, u.w - l.w, l.w);
        st_policy_f4(g_values + 4 * i, v, pol);
    }
    if (i < n_constrs4) {
        st_policy_f4(g_ax + 4 * i, make_float4(0.f, 0.f, 0.f, 0.f), pol);
    }
    if (i == 0) out[0] = 0.0f;
}

// ---------------------------------------------------------------------------
// Kernel 2: segmented scatter-add. ITEMS=4: exactly one float4/int4 stream
// load per array per thread, 4 L2-direct gathers, run-length over 4, pairwise
// tail-merge (R11 win). 2x warps vs ITEMS=8 at same total MLP -> better
// coverage of the ~240cyc L2 gather latency (same lever that won in R8).
// ---------------------------------------------------------------------------
#define ITEMS 4

__global__ void __launch_bounds__(256)
spmv_kernel(const float* __restrict__ coeff,
            const int*   __restrict__ cidx,
            const int*   __restrict__ vidx,
            int nnz) {
    int base = (blockIdx.x * blockDim.x + threadIdx.x) * ITEMS;
    unsigned lane = threadIdx.x & 31u;
    bool active = base < nnz;

    int   head_key = -1;   // sentinel: never matches a real key
    int   tail_key = -2;   // distinct sentinel
    float head_acc = 0.f;
    float tail_acc = 0.f;
    bool  has_b    = false;  // head run closed inside this tile

    if (active) {
        float c[ITEMS];
        int   ci[ITEMS];
        int count;
        if (base + ITEMS <= nnz) {
            count = ITEMS;
            float4 f = *reinterpret_cast<const float4*>(coeff + base);
            int4   a = *reinterpret_cast<const int4*>(cidx + base);
            int4   b = *reinterpret_cast<const int4*>(vidx + base);
            c[0] = f.x; c[1] = f.y; c[2] = f.z; c[3] = f.w;
            ci[0] = a.x; ci[1] = a.y; ci[2] = a.z; ci[3] = a.w;
            c[0] *= __ldcg(g_values + b.x);
            c[1] *= __ldcg(g_values + b.y);
            c[2] *= __ldcg(g_values + b.z);
            c[3] *= __ldcg(g_values + b.w);
        } else {
            count = nnz - base;
            for (int j = 0; j < count; j++) {
                c[j]  = coeff[base + j] * __ldcg(g_values + vidx[base + j]);
                ci[j] = cidx[base + j];
            }
        }

        head_key = ci[0];
        int   cur = ci[0];
        float acc = c[0];
#pragma unroll
        for (int j = 1; j < ITEMS; j++) {
            if (j < count) {
                if (ci[j] == cur) {
                    acc += c[j];
                } else {
                    if (!has_b) { head_acc = acc; has_b = true; }
                    else        atomicAdd(&g_ax[cur], acc);  // interior run
                    cur = ci[j];
                    acc = c[j];
                }
            }
        }
        tail_key = cur;
        tail_acc = acc;
    }

    // ---- pairwise cross-thread merge (all lanes participate) ----
    int   prev_tail_key = __shfl_up_sync(FULLMASK, tail_key, 1);
    float prev_tail_acc = __shfl_up_sync(FULLMASK, tail_acc, 1);
    int   next_head_key = __shfl_down_sync(FULLMASK, head_key, 1);
    int   next_has_b    = __shfl_down_sync(FULLMASK, (int)has_b, 1);

    bool take_prev = (lane > 0) && has_b && (prev_tail_key == head_key);
    bool absorbed  = (lane < 31) && next_has_b && (next_head_key == tail_key);

    if (take_prev) head_acc += prev_tail_acc;

    if (active && has_b)
        atomicAdd(&g_ax[head_key], head_acc);
    if (active && !absorbed)
        atomicAdd(&g_ax[tail_key], tail_acc);
}

// ---------------------------------------------------------------------------
// Kernel 3: violations + mean reduction (vectorized, __ldcg on read-once).
// sense: 1 -> relu(ax-b), 2 -> relu(b-ax), 3 -> |ax-b|, else 0.
// ---------------------------------------------------------------------------
__global__ void loss_kernel(const float4* __restrict__ rhs,
                            const int4*   __restrict__ sense,
                            int n_constrs4, float inv_n,
                            float* __restrict__ out) {
    __shared__ float sdata[32];
    float local = 0.0f;
    int stride = gridDim.x * blockDim.x;
    const float4* ax4 = reinterpret_cast<const float4*>(g_ax);
    for (int i = blockIdx.x * blockDim.x + threadIdx.x; i < n_constrs4; i += stride) {
        float4 a = __ldcg(ax4 + i);
        float4 r = __ldcg(rhs + i);
        int4   s = __ldcg(sense + i);
        float d0 = a.x - r.x, d1 = a.y - r.y, d2 = a.z - r.z, d3 = a.w - r.w;
        float v;
        v = (s.x == 1) ? fmaxf(d0, 0.f) : (s.x == 2) ? fmaxf(-d0, 0.f) : (s.x == 3) ? fabsf(d0) : 0.f;
        local += v;
        v = (s.y == 1) ? fmaxf(d1, 0.f) : (s.y == 2) ? fmaxf(-d1, 0.f) : (s.y == 3) ? fabsf(d1) : 0.f;
        local += v;
        v = (s.z == 1) ? fmaxf(d2, 0.f) : (s.z == 2) ? fmaxf(-d2, 0.f) : (s.z == 3) ? fabsf(d2) : 0.f;
        local += v;
        v = (s.w == 1) ? fmaxf(d3, 0.f) : (s.w == 2) ? fmaxf(-d3, 0.f) : (s.w == 3) ? fabsf(d3) : 0.f;
        local += v;
    }
#pragma unroll
    for (int off = 16; off > 0; off >>= 1)
        local += __shfl_down_sync(FULLMASK, local, off);
    int lane = threadIdx.x & 31;
    int wid  = threadIdx.x >> 5;
    if (lane == 0) sdata[wid] = local;
    __syncthreads();
    int nwarps = (blockDim.x + 31) >> 5;
    if (wid == 0) {
        float v = (lane < nwarps) ? sdata[lane] : 0.0f;
#pragma unroll
        for (int off = 16; off > 0; off >>= 1)
            v += __shfl_down_sync(FULLMASK, v, off);
        if (lane == 0) atomicAdd(out, v * inv_n);
    }
}

// Tail-handling loss kernel for n_constrs not divisible by 4 (safety).
__global__ void loss_tail_kernel(const float* __restrict__ rhs,
                                 const int*   __restrict__ sense,
                                 int start, int n_constrs, float inv_n,
                                 float* __restrict__ out) {
    int i = start + blockIdx.x * blockDim.x + threadIdx.x;
    if (i < n_constrs) {
        float diff = g_ax[i] - rhs[i];
        int s = sense[i];
        float v = (s == 1) ? fmaxf(diff, 0.f)
                : (s == 2) ? fmaxf(-diff, 0.f)
                : (s == 3) ? fabsf(diff) : 0.f;
        atomicAdd(out, v * inv_n);
    }
}

// ---------------------------------------------------------------------------
// Launch. Input order: pred, coeff, constr_rhs, var_lb, var_ub,
// constr_idx, var_idx, constr_sense, n_vars, n_constrs.
// ---------------------------------------------------------------------------
extern "C" void kernel_launch(void* const* d_in, const int* in_sizes, int n_in,
                              void* d_out, int out_size) {
    const float* pred  = (const float*)d_in[0];
    const float* coeff = (const float*)d_in[1];
    const float* rhs   = (const float*)d_in[2];
    const float* lb    = (const float*)d_in[3];
    const float* ub    = (const float*)d_in[4];
    const int*   cidx  = (const int*)d_in[5];
    const int*   vidx  = (const int*)d_in[6];
    const int*   sense = (const int*)d_in[7];

    int n_vars    = in_sizes[0];
    int nnz       = in_sizes[1];
    int n_constrs = in_sizes[2];

    float* out = (float*)d_out;
    int threads = 256;

    // prep: vectorized (problem sizes are multiples of 4).
    int n_vars4    = n_vars / 4;
    int n_constrs4 = n_constrs / 4;
    int n_max4 = n_vars4 > n_constrs4 ? n_vars4 : n_constrs4;
    prep_kernel<<<(n_max4 + threads - 1) / threads, threads>>>(
        (const float4*)pred, (const float4*)lb, (const float4*)ub,
        n_vars4, n_constrs4, out);

    long long n_threads_spmv = ((long long)nnz + ITEMS - 1) / ITEMS;
    int blocks_spmv = (int)((n_threads_spmv + threads - 1) / threads);
    spmv_kernel<<<blocks_spmv, threads>>>(coeff, cidx, vidx, nnz);

    float inv_n = 1.0f / (float)n_constrs;
    int blocks_loss = 1184;  // 8 * 148 SMs
    loss_kernel<<<blocks_loss, threads>>>((const float4*)rhs, (const int4*)sense,
                                          n_constrs4, inv_n, out);
    int tail_start = n_constrs4 * 4;
    if (tail_start < n_constrs) {
        int tail = n_constrs - tail_start;
        loss_tail_kernel<<<(tail + threads - 1) / threads, threads>>>(
            rhs, sense, tail_start, n_constrs, inv_n, out);
    }
}

// round 13
// speedup vs baseline: 1.4347x; 1.0058x over previous
#include <cuda_runtime.h>

// Problem-fixed sizes (from reference setup_inputs).
#define MAX_N_VARS    1000000
#define MAX_N_CONSTRS 1000000
#define FULLMASK 0xffffffffu

// Scratch (allocs forbidden -> __device__ globals).
__device__ float g_values[MAX_N_VARS];
__device__ float g_ax[MAX_N_CONSTRS];

// ---------------------------------------------------------------------------
// Kernel 1: values = pred*(ub-lb)+lb ; zero ax ; zero out scalar.
// ---------------------------------------------------------------------------
__global__ void prep_kernel(const float4* __restrict__ pred,
                            const float4* __restrict__ lb,
                            const float4* __restrict__ ub,
                            int n_vars4, int n_constrs4,
                            float* __restrict__ out) {
    int i = blockIdx.x * blockDim.x + threadIdx.x;
    if (i < n_vars4) {
        float4 p = __ldcg(pred + i);
        float4 l = __ldcg(lb + i);
        float4 u = __ldcg(ub + i);
        float4 v;
        v.x = fmaf(p.x, u.x - l.x, l.x);
        v.y = fmaf(p.y, u.y - l.y, l.y);
        v.z = fmaf(p.z, u.z - l.z, l.z);
        v.w = fmaf(p.w, u.w - l.w, l.w);
        reinterpret_cast<float4*>(g_values)[i] = v;
    }
    if (i < n_constrs4) {
        reinterpret_cast<float4*>(g_ax)[i] = make_float4(0.f, 0.f, 0.f, 0.f);
    }
    if (i == 0) out[0] = 0.0f;
}

// ---------------------------------------------------------------------------
// Kernel 2: segmented scatter-add. ITEMS=4 champion (at the L1tex wavefront
// floor: ~1 random gather wavefront / cyc / SM). Pairwise + 2-hop tail-merge:
// a "pass-through" neighbor (whole tile = one run, !has_b) lets the closing
// thread absorb TWO predecessor tails. ~4.3M -> ~3.2M atomics.
// ---------------------------------------------------------------------------
#define ITEMS 4

__global__ void __launch_bounds__(256)
spmv_kernel(const float* __restrict__ coeff,
            const int*   __restrict__ cidx,
            const int*   __restrict__ vidx,
            int nnz) {
    int base = (blockIdx.x * blockDim.x + threadIdx.x) * ITEMS;
    unsigned lane = threadIdx.x & 31u;
    bool active = base < nnz;

    int   head_key = -1;   // sentinel: never matches a real key
    int   tail_key = -2;   // distinct sentinel (also breaks passthrough test)
    float head_acc = 0.f;
    float tail_acc = 0.f;
    bool  has_b    = false;  // head run closed inside this tile

    if (active) {
        float c[ITEMS];
        int   ci[ITEMS];
        int count;
        if (base + ITEMS <= nnz) {
            count = ITEMS;
            float4 f = *reinterpret_cast<const float4*>(coeff + base);
            int4   a = *reinterpret_cast<const int4*>(cidx + base);
            int4   b = *reinterpret_cast<const int4*>(vidx + base);
            c[0] = f.x; c[1] = f.y; c[2] = f.z; c[3] = f.w;
            ci[0] = a.x; ci[1] = a.y; ci[2] = a.z; ci[3] = a.w;
            c[0] *= __ldcg(g_values + b.x);
            c[1] *= __ldcg(g_values + b.y);
            c[2] *= __ldcg(g_values + b.z);
            c[3] *= __ldcg(g_values + b.w);
        } else {
            count = nnz - base;
            for (int j = 0; j < count; j++) {
                c[j]  = coeff[base + j] * __ldcg(g_values + vidx[base + j]);
                ci[j] = cidx[base + j];
            }
        }

        head_key = ci[0];
        int   cur = ci[0];
        float acc = c[0];
#pragma unroll
        for (int j = 1; j < ITEMS; j++) {
            if (j < count) {
                if (ci[j] == cur) {
                    acc += c[j];
                } else {
                    if (!has_b) { head_acc = acc; has_b = true; }
                    else        atomicAdd(&g_ax[cur], acc);  // interior run
                    cur = ci[j];
                    acc = c[j];
                }
            }
        }
        tail_key = cur;
        tail_acc = acc;
    }

    // ---- cross-thread merge (all lanes participate in shuffles) ----
    // passthrough: whole tile is a single run (head==tail, nothing closed).
    bool pass = (head_key == tail_key) && !has_b;

    int   prev_tail_key  = __shfl_up_sync(FULLMASK, tail_key, 1);
    float prev_tail_acc  = __shfl_up_sync(FULLMASK, tail_acc, 1);
    int   prev_pass      = __shfl_up_sync(FULLMASK, (int)pass, 1);
    int   prev2_tail_key = __shfl_up_sync(FULLMASK, tail_key, 2);
    float prev2_tail_acc = __shfl_up_sync(FULLMASK, tail_acc, 2);

    int   next_head_key  = __shfl_down_sync(FULLMASK, head_key, 1);
    int   next_has_b     = __shfl_down_sync(FULLMASK, (int)has_b, 1);
    int   next_pass      = __shfl_down_sync(FULLMASK, (int)pass, 1);
    int   next2_head_key = __shfl_down_sync(FULLMASK, head_key, 2);
    int   next2_has_b    = __shfl_down_sync(FULLMASK, (int)has_b, 2);

    // 1-hop: absorb immediate predecessor's tail into my head run.
    bool take_prev  = (lane > 0) && has_b && (prev_tail_key == head_key);
    // 2-hop: predecessor-of-predecessor's tail hops over a passthrough lane.
    bool take_prev2 = (lane > 1) && has_b && prev_pass &&
                      (prev2_tail_key == head_key);
    // My tail is absorbed iff the matching absorber takes it (mirror logic).
    bool absorbed1 = (lane < 31) && next_has_b && (next_head_key == tail_key);
    bool absorbed2 = (lane < 30) && next_pass && next2_has_b &&
                     (next2_head_key == tail_key);

    if (take_prev)  head_acc += prev_tail_acc;
    if (take_prev2) head_acc += prev2_tail_acc;

    if (active && has_b)
        atomicAdd(&g_ax[head_key], head_acc);
    if (active && !(absorbed1 || absorbed2))
        atomicAdd(&g_ax[tail_key], tail_acc);
}

// ---------------------------------------------------------------------------
// Kernel 3: violations + mean reduction (vectorized, __ldcg on read-once),
// exact 1:1 grid (no stride loop).
// sense: 1 -> relu(ax-b), 2 -> relu(b-ax), 3 -> |ax-b|, else 0.
// ---------------------------------------------------------------------------
__global__ void loss_kernel(const float4* __restrict__ rhs,
                            const int4*   __restrict__ sense,
                            int n_constrs4, float inv_n,
                            float* __restrict__ out) {
    __shared__ float sdata[32];
    float local = 0.0f;
    int i = blockIdx.x * blockDim.x + threadIdx.x;
    const float4* ax4 = reinterpret_cast<const float4*>(g_ax);
    if (i < n_constrs4) {
        float4 a = __ldcg(ax4 + i);
        float4 r = __ldcg(rhs + i);
        int4   s = __ldcg(sense + i);
        float d0 = a.x - r.x, d1 = a.y - r.y, d2 = a.z - r.z, d3 = a.w - r.w;
        float v;
        v = (s.x == 1) ? fmaxf(d0, 0.f) : (s.x == 2) ? fmaxf(-d0, 0.f) : (s.x == 3) ? fabsf(d0) : 0.f;
        local += v;
        v = (s.y == 1) ? fmaxf(d1, 0.f) : (s.y == 2) ? fmaxf(-d1, 0.f) : (s.y == 3) ? fabsf(d1) : 0.f;
        local += v;
        v = (s.z == 1) ? fmaxf(d2, 0.f) : (s.z == 2) ? fmaxf(-d2, 0.f) : (s.z == 3) ? fabsf(d2) : 0.f;
        local += v;
        v = (s.w == 1) ? fmaxf(d3, 0.f) : (s.w == 2) ? fmaxf(-d3, 0.f) : (s.w == 3) ? fabsf(d3) : 0.f;
        local += v;
    }
#pragma unroll
    for (int off = 16; off > 0; off >>= 1)
        local += __shfl_down_sync(FULLMASK, local, off);
    int lane = threadIdx.x & 31;
    int wid  = threadIdx.x >> 5;
    if (lane == 0) sdata[wid] = local;
    __syncthreads();
    int nwarps = (blockDim.x + 31) >> 5;
    if (wid == 0) {
        float v = (lane < nwarps) ? sdata[lane] : 0.0f;
#pragma unroll
        for (int off = 16; off > 0; off >>= 1)
            v += __shfl_down_sync(FULLMASK, v, off);
        if (lane == 0) atomicAdd(out, v * inv_n);
    }
}

// Tail-handling loss kernel for n_constrs not divisible by 4 (safety;
// never launched for the fixed 1M size).
__global__ void loss_tail_kernel(const float* __restrict__ rhs,
                                 const int*   __restrict__ sense,
                                 int start, int n_constrs, float inv_n,
                                 float* __restrict__ out) {
    int i = start + blockIdx.x * blockDim.x + threadIdx.x;
    if (i < n_constrs) {
        float diff = g_ax[i] - rhs[i];
        int s = sense[i];
        float v = (s == 1) ? fmaxf(diff, 0.f)
                : (s == 2) ? fmaxf(-diff, 0.f)
                : (s == 3) ? fabsf(diff) : 0.f;
        atomicAdd(out, v * inv_n);
    }
}

// ---------------------------------------------------------------------------
// Launch. Input order: pred, coeff, constr_rhs, var_lb, var_ub,
// constr_idx, var_idx, constr_sense, n_vars, n_constrs.
// ---------------------------------------------------------------------------
extern "C" void kernel_launch(void* const* d_in, const int* in_sizes, int n_in,
                              void* d_out, int out_size) {
    const float* pred  = (const float*)d_in[0];
    const float* coeff = (const float*)d_in[1];
    const float* rhs   = (const float*)d_in[2];
    const float* lb    = (const float*)d_in[3];
    const float* ub    = (const float*)d_in[4];
    const int*   cidx  = (const int*)d_in[5];
    const int*   vidx  = (const int*)d_in[6];
    const int*   sense = (const int*)d_in[7];

    int n_vars    = in_sizes[0];
    int nnz       = in_sizes[1];
    int n_constrs = in_sizes[2];

    float* out = (float*)d_out;
    int threads = 256;

    // prep: vectorized (problem sizes are multiples of 4).
    int n_vars4    = n_vars / 4;
    int n_constrs4 = n_constrs / 4;
    int n_max4 = n_vars4 > n_constrs4 ? n_vars4 : n_constrs4;
    prep_kernel<<<(n_max4 + threads - 1) / threads, threads>>>(
        (const float4*)pred, (const float4*)lb, (const float4*)ub,
        n_vars4, n_constrs4, out);

    long long n_threads_spmv = ((long long)nnz + ITEMS - 1) / ITEMS;
    int blocks_spmv = (int)((n_threads_spmv + threads - 1) / threads);
    spmv_kernel<<<blocks_spmv, threads>>>(coeff, cidx, vidx, nnz);

    float inv_n = 1.0f / (float)n_constrs;
    int blocks_loss = (n_constrs4 + threads - 1) / threads;
    loss_kernel<<<blocks_loss, threads>>>((const float4*)rhs, (const int4*)sense,
                                          n_constrs4, inv_n, out);
    int tail_start = n_constrs4 * 4;
    if (tail_start < n_constrs) {
        int tail = n_constrs - tail_start;
        loss_tail_kernel<<<(tail + threads - 1) / threads, threads>>>(
            rhs, sense, tail_start, n_constrs, inv_n, out);
    }
}

// round 14
// speedup vs baseline: 1.4606x; 1.0180x over previous
#include <cuda_runtime.h>

// Problem-fixed sizes (from reference setup_inputs).
#define MAX_N_VARS    1000000
#define MAX_N_CONSTRS 1000000
#define FULLMASK 0xffffffffu

// Scratch (allocs forbidden -> __device__ globals).
__device__ float g_values[MAX_N_VARS];
__device__ float g_ax[MAX_N_CONSTRS];

// ---------------------------------------------------------------------------
// Kernel 1: values = pred*(ub-lb)+lb ; zero ax ; zero out scalar.
// Triggers PDL immediately so the SpMV grid can launch and start its
// independent stream loads while this kernel runs.
// ---------------------------------------------------------------------------
__global__ void prep_kernel(const float4* __restrict__ pred,
                            const float4* __restrict__ lb,
                            const float4* __restrict__ ub,
                            int n_vars4, int n_constrs4,
                            float* __restrict__ out) {
    cudaTriggerProgrammaticLaunchCompletion();
    int i = blockIdx.x * blockDim.x + threadIdx.x;
    if (i < n_vars4) {
        float4 p = __ldcg(pred + i);
        float4 l = __ldcg(lb + i);
        float4 u = __ldcg(ub + i);
        float4 v;
        v.x = fmaf(p.x, u.x - l.x, l.x);
        v.y = fmaf(p.y, u.y - l.y, l.y);
        v.z = fmaf(p.z, u.z - l.z, l.z);
        v.w = fmaf(p.w, u.w - l.w, l.w);
        reinterpret_cast<float4*>(g_values)[i] = v;
    }
    if (i < n_constrs4) {
        reinterpret_cast<float4*>(g_ax)[i] = make_float4(0.f, 0.f, 0.f, 0.f);
    }
    if (i == 0) out[0] = 0.0f;
}

// ---------------------------------------------------------------------------
// Kernel 2: segmented scatter-add. ITEMS=4 champion (at the L1tex wavefront
// floor). PDL: stream loads (independent of prep) issue BEFORE
// cudaGridDependencySynchronize(); gathers (need g_values) and atomics
// (need zeroed g_ax) after. Pairwise + 2-hop tail-merge (R11/R13 wins).
// Triggers its own PDL completion so loss can prefetch rhs/sense.
// ---------------------------------------------------------------------------
#define ITEMS 4

__global__ void __launch_bounds__(256)
spmv_kernel(const float* __restrict__ coeff,
            const int*   __restrict__ cidx,
            const int*   __restrict__ vidx,
            int nnz) {
    int base = (blockIdx.x * blockDim.x + threadIdx.x) * ITEMS;
    unsigned lane = threadIdx.x & 31u;
    bool active = base < nnz;
    bool full = active && (base + ITEMS <= nnz);

    // ---- phase 1: stream loads (do NOT depend on prep) ----
    float c[ITEMS];
    int   ci[ITEMS];
    int4  b = make_int4(0, 0, 0, 0);
    int   count = 0;
    if (full) {
        count = ITEMS;
        float4 f = *reinterpret_cast<const float4*>(coeff + base);
        int4   a = *reinterpret_cast<const int4*>(cidx + base);
        b = *reinterpret_cast<const int4*>(vidx + base);
        c[0] = f.x; c[1] = f.y; c[2] = f.z; c[3] = f.w;
        ci[0] = a.x; ci[1] = a.y; ci[2] = a.z; ci[3] = a.w;
    } else if (active) {
        count = nnz - base;
        for (int j = 0; j < count; j++) {
            c[j]  = coeff[base + j];
            ci[j] = cidx[base + j];
        }
    }

    cudaTriggerProgrammaticLaunchCompletion();
    // ---- wait for prep (g_values complete, g_ax zeroed) ----
    cudaGridDependencySynchronize();

    int   head_key = -1;   // sentinel: never matches a real key
    int   tail_key = -2;   // distinct sentinel (also breaks passthrough test)
    float head_acc = 0.f;
    float tail_acc = 0.f;
    bool  has_b    = false;  // head run closed inside this tile

    if (active) {
        if (full) {
            c[0] *= __ldcg(g_values + b.x);
            c[1] *= __ldcg(g_values + b.y);
            c[2] *= __ldcg(g_values + b.z);
            c[3] *= __ldcg(g_values + b.w);
        } else {
            for (int j = 0; j < count; j++)
                c[j] *= __ldcg(g_values + vidx[base + j]);
        }

        head_key = ci[0];
        int   cur = ci[0];
        float acc = c[0];
#pragma unroll
        for (int j = 1; j < ITEMS; j++) {
            if (j < count) {
                if (ci[j] == cur) {
                    acc += c[j];
                } else {
                    if (!has_b) { head_acc = acc; has_b = true; }
                    else        atomicAdd(&g_ax[cur], acc);  // interior run
                    cur = ci[j];
                    acc = c[j];
                }
            }
        }
        tail_key = cur;
        tail_acc = acc;
    }

    // ---- cross-thread merge (all lanes participate in shuffles) ----
    bool pass = (head_key == tail_key) && !has_b;

    int   prev_tail_key  = __shfl_up_sync(FULLMASK, tail_key, 1);
    float prev_tail_acc  = __shfl_up_sync(FULLMASK, tail_acc, 1);
    int   prev_pass      = __shfl_up_sync(FULLMASK, (int)pass, 1);
    int   prev2_tail_key = __shfl_up_sync(FULLMASK, tail_key, 2);
    float prev2_tail_acc = __shfl_up_sync(FULLMASK, tail_acc, 2);

    int   next_head_key  = __shfl_down_sync(FULLMASK, head_key, 1);
    int   next_has_b     = __shfl_down_sync(FULLMASK, (int)has_b, 1);
    int   next_pass      = __shfl_down_sync(FULLMASK, (int)pass, 1);
    int   next2_head_key = __shfl_down_sync(FULLMASK, head_key, 2);
    int   next2_has_b    = __shfl_down_sync(FULLMASK, (int)has_b, 2);

    bool take_prev  = (lane > 0) && has_b && (prev_tail_key == head_key);
    bool take_prev2 = (lane > 1) && has_b && prev_pass &&
                      (prev2_tail_key == head_key);
    bool absorbed1 = (lane < 31) && next_has_b && (next_head_key == tail_key);
    bool absorbed2 = (lane < 30) && next_pass && next2_has_b &&
                     (next2_head_key == tail_key);

    if (take_prev)  head_acc += prev_tail_acc;
    if (take_prev2) head_acc += prev2_tail_acc;

    if (active && has_b)
        atomicAdd(&g_ax[head_key], head_acc);
    if (active && !(absorbed1 || absorbed2))
        atomicAdd(&g_ax[tail_key], tail_acc);
}

// ---------------------------------------------------------------------------
// Kernel 3: violations + mean reduction. PDL: rhs/sense loads (independent of
// spmv) issue before the dependency sync; g_ax read after.
// sense: 1 -> relu(ax-b), 2 -> relu(b-ax), 3 -> |ax-b|, else 0.
// ---------------------------------------------------------------------------
__global__ void loss_kernel(const float4* __restrict__ rhs,
                            const int4*   __restrict__ sense,
                            int n_constrs4, float inv_n,
                            float* __restrict__ out) {
    __shared__ float sdata[32];
    int i = blockIdx.x * blockDim.x + threadIdx.x;
    bool active = i < n_constrs4;

    float4 r = make_float4(0.f, 0.f, 0.f, 0.f);
    int4   s = make_int4(0, 0, 0, 0);
    if (active) {
        r = __ldcg(rhs + i);
        s = __ldcg(sense + i);
    }

    cudaGridDependencySynchronize();  // wait for spmv (g_ax complete)

    float local = 0.0f;
    if (active) {
        float4 a = __ldcg(reinterpret_cast<const float4*>(g_ax) + i);
        float d0 = a.x - r.x, d1 = a.y - r.y, d2 = a.z - r.z, d3 = a.w - r.w;
        float v;
        v = (s.x == 1) ? fmaxf(d0, 0.f) : (s.x == 2) ? fmaxf(-d0, 0.f) : (s.x == 3) ? fabsf(d0) : 0.f;
        local += v;
        v = (s.y == 1) ? fmaxf(d1, 0.f) : (s.y == 2) ? fmaxf(-d1, 0.f) : (s.y == 3) ? fabsf(d1) : 0.f;
        local += v;
        v = (s.z == 1) ? fmaxf(d2, 0.f) : (s.z == 2) ? fmaxf(-d2, 0.f) : (s.z == 3) ? fabsf(d2) : 0.f;
        local += v;
        v = (s.w == 1) ? fmaxf(d3, 0.f) : (s.w == 2) ? fmaxf(-d3, 0.f) : (s.w == 3) ? fabsf(d3) : 0.f;
        local += v;
    }
#pragma unroll
    for (int off = 16; off > 0; off >>= 1)
        local += __shfl_down_sync(FULLMASK, local, off);
    int lane = threadIdx.x & 31;
    int wid  = threadIdx.x >> 5;
    if (lane == 0) sdata[wid] = local;
    __syncthreads();
    int nwarps = (blockDim.x + 31) >> 5;
    if (wid == 0) {
        float v = (lane < nwarps) ? sdata[lane] : 0.0f;
#pragma unroll
        for (int off = 16; off > 0; off >>= 1)
            v += __shfl_down_sync(FULLMASK, v, off);
        if (lane == 0) atomicAdd(out, v * inv_n);
    }
}

// Tail-handling loss kernel (safety; never launched for the fixed 1M size).
__global__ void loss_tail_kernel(const float* __restrict__ rhs,
                                 const int*   __restrict__ sense,
                                 int start, int n_constrs, float inv_n,
                                 float* __restrict__ out) {
    int i = start + blockIdx.x * blockDim.x + threadIdx.x;
    if (i < n_constrs) {
        float diff = g_ax[i] - rhs[i];
        int sv = sense[i];
        float v = (sv == 1) ? fmaxf(diff, 0.f)
                : (sv == 2) ? fmaxf(-diff, 0.f)
                : (sv == 3) ? fabsf(diff) : 0.f;
        atomicAdd(out, v * inv_n);
    }
}

// ---------------------------------------------------------------------------
// Launch. Input order: pred, coeff, constr_rhs, var_lb, var_ub,
// constr_idx, var_idx, constr_sense, n_vars, n_constrs.
// prep -> spmv -> loss chained with Programmatic Dependent Launch.
// ---------------------------------------------------------------------------
extern "C" void kernel_launch(void* const* d_in, const int* in_sizes, int n_in,
                              void* d_out, int out_size) {
    const float* pred  = (const float*)d_in[0];
    const float* coeff = (const float*)d_in[1];
    const float* rhs   = (const float*)d_in[2];
    const float* lb    = (const float*)d_in[3];
    const float* ub    = (const float*)d_in[4];
    const int*   cidx  = (const int*)d_in[5];
    const int*   vidx  = (const int*)d_in[6];
    const int*   sense = (const int*)d_in[7];

    int n_vars    = in_sizes[0];
    int nnz       = in_sizes[1];
    int n_constrs = in_sizes[2];

    float* out = (float*)d_out;
    int threads = 256;

    int n_vars4    = n_vars / 4;
    int n_constrs4 = n_constrs / 4;
    int n_max4 = n_vars4 > n_constrs4 ? n_vars4 : n_constrs4;

    // prep: plain launch (first in chain).
    prep_kernel<<<(n_max4 + threads - 1) / threads, threads>>>(
        (const float4*)pred, (const float4*)lb, (const float4*)ub,
        n_vars4, n_constrs4, out);

    cudaLaunchAttribute pdl_attr[1];
    pdl_attr[0].id = cudaLaunchAttributeProgrammaticStreamSerialization;
    pdl_attr[0].val.programmaticStreamSerializationAllowed = 1;

    // spmv: PDL launch (overlaps its stream loads with prep).
    {
        long long n_threads_spmv = ((long long)nnz + ITEMS - 1) / ITEMS;
        int blocks_spmv = (int)((n_threads_spmv + threads - 1) / threads);
        cudaLaunchConfig_t cfg = {};
        cfg.gridDim = dim3(blocks_spmv, 1, 1);
        cfg.blockDim = dim3(threads, 1, 1);
        cfg.attrs = pdl_attr;
        cfg.numAttrs = 1;
        cudaLaunchKernelEx(&cfg, spmv_kernel, coeff, cidx, vidx, nnz);
    }

    // loss: PDL launch (overlaps rhs/sense loads with spmv tail).
    float inv_n = 1.0f / (float)n_constrs;
    {
        int blocks_loss = (n_constrs4 + threads - 1) / threads;
        cudaLaunchConfig_t cfg = {};
        cfg.gridDim = dim3(blocks_loss, 1, 1);
        cfg.blockDim = dim3(threads, 1, 1);
        cfg.attrs = pdl_attr;
        cfg.numAttrs = 1;
        cudaLaunchKernelEx(&cfg, loss_kernel,
                           (const float4*)rhs, (const int4*)sense,
                           n_constrs4, inv_n, out);
    }

    int tail_start = n_constrs4 * 4;
    if (tail_start < n_constrs) {
        int tail = n_constrs - tail_start;
        loss_tail_kernel<<<(tail + threads - 1) / threads, threads>>>(
            rhs, sense, tail_start, n_constrs, inv_n, out);
    }
}

// round 15
// speedup vs baseline: 1.4612x; 1.0004x over previous
#include <cuda_runtime.h>

// Problem-fixed sizes (from reference setup_inputs).
#define MAX_N_VARS    1000000
#define MAX_N_CONSTRS 1000000
#define FULLMASK 0xffffffffu

// Scratch (allocs forbidden -> __device__ globals).
__device__ float g_values[MAX_N_VARS];
__device__ float g_ax[MAX_N_CONSTRS];

// ---------------------------------------------------------------------------
// Kernel 1: values = pred*(ub-lb)+lb ; zero ax ; zero out scalar.
// Triggers PDL immediately so the SpMV grid can launch while this runs.
// ---------------------------------------------------------------------------
__global__ void prep_kernel(const float4* __restrict__ pred,
                            const float4* __restrict__ lb,
                            const float4* __restrict__ ub,
                            int n_vars4, int n_constrs4,
                            float* __restrict__ out) {
    cudaTriggerProgrammaticLaunchCompletion();
    int i = blockIdx.x * blockDim.x + threadIdx.x;
    if (i < n_vars4) {
        float4 p = __ldcg(pred + i);
        float4 l = __ldcg(lb + i);
        float4 u = __ldcg(ub + i);
        float4 v;
        v.x = fmaf(p.x, u.x - l.x, l.x);
        v.y = fmaf(p.y, u.y - l.y, l.y);
        v.z = fmaf(p.z, u.z - l.z, l.z);
        v.w = fmaf(p.w, u.w - l.w, l.w);
        reinterpret_cast<float4*>(g_values)[i] = v;
    }
    if (i < n_constrs4) {
        reinterpret_cast<float4*>(g_ax)[i] = make_float4(0.f, 0.f, 0.f, 0.f);
    }
    if (i == 0) out[0] = 0.0f;
}

// ---------------------------------------------------------------------------
// Kernel 2: segmented scatter-add. ITEMS=4 (at the L1tex wavefront floor).
// PDL: trigger at ENTRY (lets loss launch earliest); stream loads
// (independent of prep) issue before cudaGridDependencySynchronize();
// gathers + atomics after. Pairwise + 2-hop tail-merge. blockDim=512.
// ---------------------------------------------------------------------------
#define ITEMS 4
#define SPMV_THREADS 512

__global__ void __launch_bounds__(SPMV_THREADS)
spmv_kernel(const float* __restrict__ coeff,
            const int*   __restrict__ cidx,
            const int*   __restrict__ vidx,
            int nnz) {
    cudaTriggerProgrammaticLaunchCompletion();

    int base = (blockIdx.x * blockDim.x + threadIdx.x) * ITEMS;
    unsigned lane = threadIdx.x & 31u;
    bool active = base < nnz;
    bool full = active && (base + ITEMS <= nnz);

    // ---- phase 1: stream loads (do NOT depend on prep) ----
    float c[ITEMS];
    int   ci[ITEMS];
    int4  b = make_int4(0, 0, 0, 0);
    int   count = 0;
    if (full) {
        count = ITEMS;
        float4 f = *reinterpret_cast<const float4*>(coeff + base);
        int4   a = *reinterpret_cast<const int4*>(cidx + base);
        b = *reinterpret_cast<const int4*>(vidx + base);
        c[0] = f.x; c[1] = f.y; c[2] = f.z; c[3] = f.w;
        ci[0] = a.x; ci[1] = a.y; ci[2] = a.z; ci[3] = a.w;
    } else if (active) {
        count = nnz - base;
        for (int j = 0; j < count; j++) {
            c[j]  = coeff[base + j];
            ci[j] = cidx[base + j];
        }
    }

    // ---- wait for prep (g_values complete, g_ax zeroed) ----
    cudaGridDependencySynchronize();

    int   head_key = -1;   // sentinel: never matches a real key
    int   tail_key = -2;   // distinct sentinel (also breaks passthrough test)
    float head_acc = 0.f;
    float tail_acc = 0.f;
    bool  has_b    = false;  // head run closed inside this tile

    if (active) {
        if (full) {
            c[0] *= __ldcg(g_values + b.x);
            c[1] *= __ldcg(g_values + b.y);
            c[2] *= __ldcg(g_values + b.z);
            c[3] *= __ldcg(g_values + b.w);
        } else {
            for (int j = 0; j < count; j++)
                c[j] *= __ldcg(g_values + vidx[base + j]);
        }

        head_key = ci[0];
        int   cur = ci[0];
        float acc = c[0];
#pragma unroll
        for (int j = 1; j < ITEMS; j++) {
            if (j < count) {
                if (ci[j] == cur) {
                    acc += c[j];
                } else {
                    if (!has_b) { head_acc = acc; has_b = true; }
                    else        atomicAdd(&g_ax[cur], acc);  // interior run
                    cur = ci[j];
                    acc = c[j];
                }
            }
        }
        tail_key = cur;
        tail_acc = acc;
    }

    // ---- cross-thread merge (all lanes participate in shuffles) ----
    bool pass = (head_key == tail_key) && !has_b;

    int   prev_tail_key  = __shfl_up_sync(FULLMASK, tail_key, 1);
    float prev_tail_acc  = __shfl_up_sync(FULLMASK, tail_acc, 1);
    int   prev_pass      = __shfl_up_sync(FULLMASK, (int)pass, 1);
    int   prev2_tail_key = __shfl_up_sync(FULLMASK, tail_key, 2);
    float prev2_tail_acc = __shfl_up_sync(FULLMASK, tail_acc, 2);

    int   next_head_key  = __shfl_down_sync(FULLMASK, head_key, 1);
    int   next_has_b     = __shfl_down_sync(FULLMASK, (int)has_b, 1);
    int   next_pass      = __shfl_down_sync(FULLMASK, (int)pass, 1);
    int   next2_head_key = __shfl_down_sync(FULLMASK, head_key, 2);
    int   next2_has_b    = __shfl_down_sync(FULLMASK, (int)has_b, 2);

    bool take_prev  = (lane > 0) && has_b && (prev_tail_key == head_key);
    bool take_prev2 = (lane > 1) && has_b && prev_pass &&
                      (prev2_tail_key == head_key);
    bool absorbed1 = (lane < 31) && next_has_b && (next_head_key == tail_key);
    bool absorbed2 = (lane < 30) && next_pass && next2_has_b &&
                     (next2_head_key == tail_key);

    if (take_prev)  head_acc += prev_tail_acc;
    if (take_prev2) head_acc += prev2_tail_acc;

    if (active && has_b)
        atomicAdd(&g_ax[head_key], head_acc);
    if (active && !(absorbed1 || absorbed2))
        atomicAdd(&g_ax[tail_key], tail_acc);
}

// ---------------------------------------------------------------------------
// Kernel 3: violations + mean reduction. PDL: rhs/sense loads (independent of
// spmv) issue before the dependency sync; g_ax read after. blockDim=512.
// sense: 1 -> relu(ax-b), 2 -> relu(b-ax), 3 -> |ax-b|, else 0.
// ---------------------------------------------------------------------------
#define LOSS_THREADS 512

__global__ void __launch_bounds__(LOSS_THREADS)
loss_kernel(const float4* __restrict__ rhs,
            const int4*   __restrict__ sense,
            int n_constrs4, float inv_n,
            float* __restrict__ out) {
    __shared__ float sdata[LOSS_THREADS / 32];
    int i = blockIdx.x * blockDim.x + threadIdx.x;
    bool active = i < n_constrs4;

    float4 r = make_float4(0.f, 0.f, 0.f, 0.f);
    int4   s = make_int4(0, 0, 0, 0);
    if (active) {
        r = __ldcg(rhs + i);
        s = __ldcg(sense + i);
    }

    cudaGridDependencySynchronize();  // wait for spmv (g_ax complete)

    float local = 0.0f;
    if (active) {
        float4 a = __ldcg(reinterpret_cast<const float4*>(g_ax) + i);
        float d0 = a.x - r.x, d1 = a.y - r.y, d2 = a.z - r.z, d3 = a.w - r.w;
        float v;
        v = (s.x == 1) ? fmaxf(d0, 0.f) : (s.x == 2) ? fmaxf(-d0, 0.f) : (s.x == 3) ? fabsf(d0) : 0.f;
        local += v;
        v = (s.y == 1) ? fmaxf(d1, 0.f) : (s.y == 2) ? fmaxf(-d1, 0.f) : (s.y == 3) ? fabsf(d1) : 0.f;
        local += v;
        v = (s.z == 1) ? fmaxf(d2, 0.f) : (s.z == 2) ? fmaxf(-d2, 0.f) : (s.z == 3) ? fabsf(d2) : 0.f;
        local += v;
        v = (s.w == 1) ? fmaxf(d3, 0.f) : (s.w == 2) ? fmaxf(-d3, 0.f) : (s.w == 3) ? fabsf(d3) : 0.f;
        local += v;
    }
#pragma unroll
    for (int off = 16; off > 0; off >>= 1)
        local += __shfl_down_sync(FULLMASK, local, off);
    int lane = threadIdx.x & 31;
    int wid  = threadIdx.x >> 5;
    if (lane == 0) sdata[wid] = local;
    __syncthreads();
    int nwarps = LOSS_THREADS / 32;
    if (wid == 0) {
        float v = (lane < nwarps) ? sdata[lane] : 0.0f;
#pragma unroll
        for (int off = 16; off > 0; off >>= 1)
            v += __shfl_down_sync(FULLMASK, v, off);
        if (lane == 0) atomicAdd(out, v * inv_n);
    }
}

// Tail-handling loss kernel (safety; never launched for the fixed 1M size).
__global__ void loss_tail_kernel(const float* __restrict__ rhs,
                                 const int*   __restrict__ sense,
                                 int start, int n_constrs, float inv_n,
                                 float* __restrict__ out) {
    int i = start + blockIdx.x * blockDim.x + threadIdx.x;
    if (i < n_constrs) {
        float diff = g_ax[i] - rhs[i];
        int sv = sense[i];
        float v = (sv == 1) ? fmaxf(diff, 0.f)
                : (sv == 2) ? fmaxf(-diff, 0.f)
                : (sv == 3) ? fabsf(diff) : 0.f;
        atomicAdd(out, v * inv_n);
    }
}

// ---------------------------------------------------------------------------
// Launch. Input order: pred, coeff, constr_rhs, var_lb, var_ub,
// constr_idx, var_idx, constr_sense, n_vars, n_constrs.
// prep -> spmv -> loss chained with Programmatic Dependent Launch.
// ---------------------------------------------------------------------------
extern "C" void kernel_launch(void* const* d_in, const int* in_sizes, int n_in,
                              void* d_out, int out_size) {
    const float* pred  = (const float*)d_in[0];
    const float* coeff = (const float*)d_in[1];
    const float* rhs   = (const float*)d_in[2];
    const float* lb    = (const float*)d_in[3];
    const float* ub    = (const float*)d_in[4];
    const int*   cidx  = (const int*)d_in[5];
    const int*   vidx  = (const int*)d_in[6];
    const int*   sense = (const int*)d_in[7];

    int n_vars    = in_sizes[0];
    int nnz       = in_sizes[1];
    int n_constrs = in_sizes[2];

    float* out = (float*)d_out;

    int n_vars4    = n_vars / 4;
    int n_constrs4 = n_constrs / 4;
    int n_max4 = n_vars4 > n_constrs4 ? n_vars4 : n_constrs4;

    // prep: plain launch (first in chain).
    prep_kernel<<<(n_max4 + 255) / 256, 256>>>(
        (const float4*)pred, (const float4*)lb, (const float4*)ub,
        n_vars4, n_constrs4, out);

    cudaLaunchAttribute pdl_attr[1];
    pdl_attr[0].id = cudaLaunchAttributeProgrammaticStreamSerialization;
    pdl_attr[0].val.programmaticStreamSerializationAllowed = 1;

    // spmv: PDL launch (overlaps its stream loads with prep).
    {
        long long n_threads_spmv = ((long long)nnz + ITEMS - 1) / ITEMS;
        int blocks_spmv = (int)((n_threads_spmv + SPMV_THREADS - 1) / SPMV_THREADS);
        cudaLaunchConfig_t cfg = {};
        cfg.gridDim = dim3(blocks_spmv, 1, 1);
        cfg.blockDim = dim3(SPMV_THREADS, 1, 1);
        cfg.attrs = pdl_attr;
        cfg.numAttrs = 1;
        cudaLaunchKernelEx(&cfg, spmv_kernel, coeff, cidx, vidx, nnz);
    }

    // loss: PDL launch (overlaps rhs/sense loads with spmv).
    float inv_n = 1.0f / (float)n_constrs;
    {
        int blocks_loss = (n_constrs4 + LOSS_THREADS - 1) / LOSS_THREADS;
        cudaLaunchConfig_t cfg = {};
        cfg.gridDim = dim3(blocks_loss, 1, 1);
        cfg.blockDim = dim3(LOSS_THREADS, 1, 1);
        cfg.attrs = pdl_attr;
        cfg.numAttrs = 1;
        cudaLaunchKernelEx(&cfg, loss_kernel,
                           (const float4*)rhs, (const int4*)sense,
                           n_constrs4, inv_n, out);
    }

    int tail_start = n_constrs4 * 4;
    if (tail_start < n_constrs) {
        int tail = n_constrs - tail_start;
        loss_tail_kernel<<<(tail + 255) / 256, 256>>>(
            rhs, sense, tail_start, n_constrs, inv_n, out);
    }
}